// round 8
// baseline (speedup 1.0000x reference)
#include <cuda_runtime.h>
#include <cuda_bf16.h>
#include <cstdint>

#define D_DIM   50257
#define B_Q     64
#define K_A     4096
#define NPAIR   25129            // ceil(D/2); last pair has only .x valid
#define DSPLIT  18
#define PCHUNK  1397             // ceil(NPAIR/18)
#define KT      128              // k-tile (shrunk for 2 CTAs/SM)
#define KTP     (KT + 2)         // +2 float2 pad: dp-stride 1040B kills bank conflicts
#define DP      8                // d-pairs per stage (16 d values)
#define EPSF    1e-10f
#define LN2F    0.69314718055994530942f
#define KNN     8

// ---- static device scratch (no cudaMalloc allowed) ----
__device__ float2 g_qlogP[NPAIR * B_Q];           // ~12.9 MB  (pair-major, b fast)
__device__ float  g_cross[DSPLIT * B_Q * K_A];    // ~18.9 MB  partial cross sums (ln units)
__device__ float  g_self [DSPLIT * K_A];          //  partial self sums (ln units)

// Packed dual-fp32 FMA (Blackwell f32x2 pipe): d = a*b + c on both lanes.
__device__ __forceinline__ float2 ffma2(float2 a, float2 b, float2 c) {
    unsigned long long ra = *reinterpret_cast<unsigned long long*>(&a);
    unsigned long long rb = *reinterpret_cast<unsigned long long*>(&b);
    unsigned long long rc = *reinterpret_cast<unsigned long long*>(&c);
    unsigned long long rd;
    asm("fma.rn.f32x2 %0, %1, %2, %3;" : "=l"(rd) : "l"(ra), "l"(rb), "l"(rc));
    return *reinterpret_cast<float2*>(&rd);
}

// ---------------- Kernel A: qlogP[p][b] = (ln(q[b][2p]+eps), ln(q[b][2p+1]+eps)) ----------------
__global__ void qlog_kernel(const float* __restrict__ q) {
    int idx = blockIdx.x * blockDim.x + threadIdx.x;
    if (idx >= B_Q * NPAIR) return;
    int b = idx / NPAIR;
    int p = idx % NPAIR;
    int d0 = 2 * p;
    float2 r;
    float x = q[(size_t)b * D_DIM + d0];
    r.x = __log2f(x + EPSF) * LN2F;
    r.y = 0.f;
    if (d0 + 1 < D_DIM) {
        float y = q[(size_t)b * D_DIM + d0 + 1];
        r.y = __log2f(y + EPSF) * LN2F;
    }
    g_qlogP[p * B_Q + b] = r;
}

// ---------------- Kernel B: fused cross-GEMM + self-term, 2 CTAs/SM ----------------
__global__ void __launch_bounds__(256, 2)
gemm_kernel(const float* __restrict__ anchor) {
    __shared__ __align__(16) float2 As[2][DP][KTP];  // ~16.6 KB (d-pair, local k, padded)
    __shared__ __align__(16) float2 Qs[2][DP][B_Q];  //   8 KB   (d-pair, b)

    const int tid = threadIdx.x;
    const int kb  = blockIdx.x * KT;
    const int c   = blockIdx.y;
    const int pstart = c * PCHUNK;
    const int pend   = min(pstart + PCHUNK, NPAIR);
    const int nst    = (pend - pstart + DP - 1) / DP;

    // compute mapping: 8 b-rows per warp, 4 k-columns per thread (KT=128=32*4)
    const int tx = tid & 31;
    const int ty = tid >> 5;
    const int b0 = ty * 8;

    // loader mapping: lg = 16 consecutive floats (8 d-pairs), rg = row group
    const int lg = tid & 15;          // d-pair lg>>1, component lg&1
    const int rg = tid >> 4;          // 0..15; thread's rows are rg + 16*m, m=0..7

    const int qdp = tid >> 6;         // 0..3 ; loads d-pairs qdp and qdp+4
    const int qb  = tid & 63;

    float2 acc[8][4];                 // even-d / odd-d split accumulator chains
#pragma unroll
    for (int i = 0; i < 8; ++i)
#pragma unroll
        for (int j = 0; j < 4; ++j) acc[i][j] = make_float2(0.f, 0.f);

    float selfAcc[8];                 // per owned row (rg + 16*m), this lg-float only
#pragma unroll
    for (int m = 0; m < 8; ++m) selfAcc[m] = 0.f;

    float  va[8];
    float2 qv0, qv1;

    auto loadStage = [&](int s) {
        const int p0 = pstart + s * DP;
        const int pg = p0 + (lg >> 1);
        const bool valid = (pg < pend) && !((lg & 1) && (2 * pg + 1 >= D_DIM));
        const int colf = 2 * p0 + lg;
#pragma unroll
        for (int m = 0; m < 8; ++m) {
            const float* ap = anchor + (size_t)(kb + rg + 16 * m) * D_DIM + colf;
            va[m] = valid ? __ldg(ap) : 0.f;   // warp: 2 rows x 64B contiguous per LDG
        }
        qv0 = (p0 + qdp     < pend) ? g_qlogP[(p0 + qdp    ) * B_Q + qb] : make_float2(0.f, 0.f);
        qv1 = (p0 + qdp + 4 < pend) ? g_qlogP[(p0 + qdp + 4) * B_Q + qb] : make_float2(0.f, 0.f);
    };

    auto storeStage = [&](int nb) {
        float* asbase = reinterpret_cast<float*>(&As[nb][lg >> 1][0]) + (lg & 1);
#pragma unroll
        for (int m = 0; m < 8; ++m) {
            // self term: a * ln(a+eps); padded zeros contribute exactly 0
            selfAcc[m] += va[m] * __log2f(va[m] + EPSF);
            asbase[2 * (rg + 16 * m)] = va[m];   // conflict-free STS.32 (bank = 4dp+2rg+comp)
        }
        Qs[nb][qdp    ][qb] = qv0;
        Qs[nb][qdp + 4][qb] = qv1;
    };

    loadStage(0);
    storeStage(0);
    __syncthreads();

    int buf = 0;
    for (int s = 0; s < nst; ++s) {
        const bool more = (s + 1 < nst);
        if (more) loadStage(s + 1);   // next-stage global loads in flight across FMA section

#pragma unroll 2
        for (int dp = 0; dp < DP; ++dp) {
            float2 qf[8], af[4];
            const float4* qp = reinterpret_cast<const float4*>(&Qs[buf][dp][b0]); // warp-uniform bcast
#pragma unroll
            for (int h = 0; h < 4; ++h) {
                float4 t = qp[h];
                qf[2 * h]     = make_float2(t.x, t.y);
                qf[2 * h + 1] = make_float2(t.z, t.w);
            }
#pragma unroll
            for (int j = 0; j < 4; ++j)
                af[j] = As[buf][dp][tx + 32 * j];  // lanes consecutive: conflict-free LDS.64
#pragma unroll
            for (int i = 0; i < 8; ++i)
#pragma unroll
                for (int j = 0; j < 4; ++j)
                    acc[i][j] = ffma2(qf[i], af[j], acc[i][j]);   // 2 d-steps per instr
        }

        if (more) storeStage(buf ^ 1);
        __syncthreads();
        buf ^= 1;
    }

    // ---- epilogue: self-term reduce over the 16 lg-lanes sharing each row ----
#pragma unroll
    for (int m = 0; m < 8; ++m) {
        float s = selfAcc[m];
        s += __shfl_xor_sync(0xffffffffu, s, 1);
        s += __shfl_xor_sync(0xffffffffu, s, 2);
        s += __shfl_xor_sync(0xffffffffu, s, 4);
        s += __shfl_xor_sync(0xffffffffu, s, 8);
        if (lg == 0) g_self[c * K_A + kb + rg + 16 * m] = s * LN2F;
    }
#pragma unroll
    for (int i = 0; i < 8; ++i) {
        float* dst = g_cross + ((size_t)(c * B_Q + b0 + i)) * K_A + kb;
#pragma unroll
        for (int j = 0; j < 4; ++j)
            dst[tx + 32 * j] = acc[i][j].x + acc[i][j].y;  // lanes consecutive: coalesced
    }
}

// ---------------- Kernel C: fp64 combine + top-8 argmin + majority vote ----------------
__global__ void __launch_bounds__(256)
topk_kernel(const int* __restrict__ label, float* __restrict__ out) {
    __shared__ double kl[K_A];     // 32 KB
    __shared__ double rv[256];
    __shared__ int    ri[256];
    const int b   = blockIdx.x;
    const int tid = threadIdx.x;

    for (int k = tid; k < K_A; k += 256) {
        double s = 0.0;
#pragma unroll
        for (int c = 0; c < DSPLIT; ++c)
            s += (double)g_self[c * K_A + k]
               - (double)g_cross[((size_t)(c * B_Q + b)) * K_A + k];
        kl[k] = s;   // = D * kl[b][k]; positive scaling is rank-invariant
    }
    __syncthreads();

    int cnt1 = 0;
    for (int r = 0; r < KNN; ++r) {
        double bv = 1e300; int bi = K_A - 1;
        for (int k = tid; k < K_A; k += 256) {
            double v = kl[k];
            if (v < bv) { bv = v; bi = k; }   // ascending k: lowest index wins ties (top_k semantics)
        }
        rv[tid] = bv; ri[tid] = bi;
        __syncthreads();
        for (int off = 128; off > 0; off >>= 1) {
            if (tid < off) {
                double v = rv[tid + off]; int i2 = ri[tid + off];
                if (v < rv[tid] || (v == rv[tid] && i2 < ri[tid])) { rv[tid] = v; ri[tid] = i2; }
            }
            __syncthreads();
        }
        int sel = ri[0];
        if (sel < 0)    sel = 0;
        if (sel >= K_A) sel = K_A - 1;
        cnt1 += label[sel];
        if (tid == 0) kl[sel] = 1e300;
        __syncthreads();
    }
    // knn_cnt = [8-cnt1, cnt1]; argmax ties (4-4) -> class 0; output dtype is float32
    if (tid == 0) out[b] = (cnt1 > KNN / 2) ? 1.0f : 0.0f;
}

extern "C" void kernel_launch(void* const* d_in, const int* in_sizes, int n_in,
                              void* d_out, int out_size) {
    (void)in_sizes; (void)n_in; (void)out_size;
    const float* query  = (const float*)d_in[0];
    const float* anchor = (const float*)d_in[1];
    const int*   label  = (const int*)d_in[2];
    float* out = (float*)d_out;

    qlog_kernel<<<(B_Q * NPAIR + 255) / 256, 256>>>(query);
    dim3 g(K_A / KT, DSPLIT);
    gemm_kernel<<<g, 256>>>(anchor);
    topk_kernel<<<B_Q, 256>>>(label, out);
}

// round 10
// speedup vs baseline: 1.9182x; 1.9182x over previous
#include <cuda_runtime.h>
#include <cuda_bf16.h>
#include <cstdint>

#define D_DIM   50257
#define B_Q     64
#define K_A     4096
#define KNN     8
#define EPSF    1e-10f
#define LN2F    0.69314718055994530942f

#define DSPLIT  9
#define DTILE   32
#define STAGES  175                  // ceil(50257 / (9*32))
#define CHUNK_D (STAGES * DTILE)     // 5600
#define DPAD    (DSPLIT * CHUNK_D)   // 50400
#define NTILES  (DPAD / DTILE)       // 1575
#define KTILE   128

// ---- static device scratch ----
__device__ __align__(16) unsigned short g_qB[NTILES * 4096]; // 12.9MB: per 32-d tile: [qh 4KB][ql 4KB], SW-swizzled
__device__ float g_cross[DSPLIT * B_Q * K_A];                // 9.4MB partial cross sums
__device__ float g_self [DSPLIT * K_A];

__device__ __forceinline__ uint32_t smem_u32(const void* p) {
    uint32_t a;
    asm("{ .reg .u64 t; cvta.to.shared.u64 t, %1; cvt.u32.u64 %0, t; }" : "=r"(a) : "l"(p));
    return a;
}

#define CP_ASYNC16(dst, src) asm volatile("cp.async.cg.shared.global [%0], [%1], 16;" :: "r"(dst), "l"(src))
#define CP_COMMIT()          asm volatile("cp.async.commit_group;" ::: "memory")
#define CP_WAIT0()           asm volatile("cp.async.wait_group 0;" ::: "memory")

#define LDSM_X4(r0,r1,r2,r3,a) \
    asm volatile("ldmatrix.sync.aligned.m8n8.x4.shared.b16 {%0,%1,%2,%3}, [%4];" \
        : "=r"(r0),"=r"(r1),"=r"(r2),"=r"(r3) : "r"(a))
#define LDSM_X4T(r0,r1,r2,r3,a) \
    asm volatile("ldmatrix.sync.aligned.m8n8.x4.trans.shared.b16 {%0,%1,%2,%3}, [%4];" \
        : "=r"(r0),"=r"(r1),"=r"(r2),"=r"(r3) : "r"(a))

#define MMA16816(c, a0,a1,a2,a3, b0,b1) \
    asm volatile("mma.sync.aligned.m16n8k16.row.col.f32.bf16.bf16.f32 " \
        "{%0,%1,%2,%3}, {%4,%5,%6,%7}, {%8,%9}, {%0,%1,%2,%3};" \
        : "+f"((c)[0]),"+f"((c)[1]),"+f"((c)[2]),"+f"((c)[3]) \
        : "r"(a0),"r"(a1),"r"(a2),"r"(a3), "r"(b0),"r"(b1))

// ---------------- Kernel A: qlog -> bf16 hi/lo, pre-swizzled gmem tiles ----------------
// Tile t covers d = 32t..32t+31. Layout per tile (8KB): row k=d&31 (128B), n=b columns,
// 16B chunk c=b>>3 stored at c^(k&7); lo matrix at +4096B.
__global__ void qlog_kernel(const float* __restrict__ q) {
    int idx = blockIdx.x * blockDim.x + threadIdx.x;
    if (idx >= B_Q * DPAD) return;
    int b = idx / DPAD;
    int d = idx % DPAD;
    __nv_bfloat16 hb, lb;
    if (d < D_DIM) {
        float x = __log2f(q[(size_t)b * D_DIM + d] + EPSF) * LN2F;
        hb = __float2bfloat16(x);
        lb = __float2bfloat16(x - __bfloat162float(hb));
    } else {
        hb = __float2bfloat16(0.f); lb = hb;
    }
    int t = d >> 5, k = d & 31, c = b >> 3;
    uint32_t u16off = (uint32_t)k * 64 + (uint32_t)((c ^ (k & 7)) << 3) + (b & 7); // in u16 units
    unsigned short* tb = g_qB + (size_t)t * 4096;
    tb[u16off]        = __bfloat16_as_ushort(hb);
    tb[u16off + 2048] = __bfloat16_as_ushort(lb);
}

// ---------------- Kernel B: bf16 3-chain tensor-core GEMM + fused self-term ----------------
// smem 48KB: A [2 buf][hi|lo][128 r][32 k] bf16 (buf 16KB), B at +32768 [2 buf][hi|lo][32 k][64 n] (buf 8KB)
__global__ void __launch_bounds__(256, 2)
gemm_kernel(const float* __restrict__ anchor) {
    __shared__ __align__(128) char smem[49152];
    const uint32_t sA = smem_u32(smem);
    const uint32_t sB = sA + 32768;

    const int tid  = threadIdx.x;
    const int lane = tid & 31;
    const int wid  = tid >> 5;
    const int wm   = wid >> 2;        // 0..1 : M half
    const int wn   = wid & 3;         // 0..3 : N quarter
    const int kb   = blockIdx.x * KTILE;
    const int cI   = blockIdx.y;
    const int dbase = cI * CHUNK_D;

    // loader mapping: warp owns rows wid*16 .. +15; lane: lrow = lane>>4, d-pair = lane&15
    const int lrow = lane >> 4;
    const int lcol = lane & 15;

    // ldmatrix lane constants
    const int rowA = lane & 15;                  // A: row offset within 16-row block
    const int cA   = lane >> 4;                  // A: k-chunk select
    const int swzA = ((lane & 15) >> 1) & 3;
    const int kB   = lane & 15;                  // B: k offset
    const int cB   = lane >> 4;                  // B: n-chunk select
    const int swzB = lane & 7;

    float acc[4][2][4];
#pragma unroll
    for (int mi = 0; mi < 4; ++mi)
#pragma unroll
        for (int nh = 0; nh < 2; ++nh)
#pragma unroll
            for (int r = 0; r < 4; ++r) acc[mi][nh][r] = 0.f;

    float selfAcc[8];
#pragma unroll
    for (int i = 0; i < 8; ++i) selfAcc[i] = 0.f;

    float2 va[8];

    auto loadA = [&](int s) {
        const int d0 = dbase + s * DTILE + 2 * lcol;
        const bool vx = d0 < D_DIM;
        const bool vy = d0 + 1 < D_DIM;
#pragma unroll
        for (int i = 0; i < 8; ++i) {
            const float* p = anchor + (size_t)(kb + wid * 16 + 2 * i + lrow) * D_DIM + d0;
            va[i].x = vx ? __ldg(p)     : 0.f;
            va[i].y = vy ? __ldg(p + 1) : 0.f;
        }
    };
    auto storeA = [&](int buf) {
        const uint32_t base = sA + buf * 16384;
        const uint32_t coff = (uint32_t)(lcol >> 2);          // 16B chunk of k=2*lcol
        const uint32_t within = (uint32_t)(lcol & 3) * 4;
#pragma unroll
        for (int i = 0; i < 8; ++i) {
            const int r = wid * 16 + 2 * i + lrow;
            selfAcc[i] += va[i].x * __log2f(va[i].x + EPSF)
                        + va[i].y * __log2f(va[i].y + EPSF);
            __nv_bfloat16 hx = __float2bfloat16(va[i].x);
            __nv_bfloat16 hy = __float2bfloat16(va[i].y);
            __nv_bfloat16 lx = __float2bfloat16(va[i].x - __bfloat162float(hx));
            __nv_bfloat16 ly = __float2bfloat16(va[i].y - __bfloat162float(hy));
            uint32_t ph = (uint32_t)__bfloat16_as_ushort(hx) | ((uint32_t)__bfloat16_as_ushort(hy) << 16);
            uint32_t pl = (uint32_t)__bfloat16_as_ushort(lx) | ((uint32_t)__bfloat16_as_ushort(ly) << 16);
            uint32_t swz = (uint32_t)((r >> 1) & 3);
            uint32_t byte = (uint32_t)r * 64 + ((coff ^ swz) << 4) + within;
            *(uint32_t*)(smem + buf * 16384 + byte)        = ph;
            *(uint32_t*)(smem + buf * 16384 + 8192 + byte) = pl;
        }
        (void)base;
    };
    auto issueB = [&](int s, int buf) {
        const char* src = reinterpret_cast<const char*>(g_qB) + (size_t)(cI * STAGES + s) * 8192;
        uint32_t dst = sB + buf * 8192 + tid * 16;
        CP_ASYNC16(dst, src + tid * 16);
        CP_ASYNC16(dst + 4096, src + tid * 16 + 4096);
    };

    // prologue
    loadA(0);
    issueB(0, 0);
    CP_COMMIT();
    storeA(0);
    CP_WAIT0();
    __syncthreads();

    for (int s = 0; s < STAGES; ++s) {
        const int buf = s & 1;
        const bool more = (s + 1 < STAGES);
        if (more) {
            loadA(s + 1);
            issueB(s + 1, buf ^ 1);
            CP_COMMIT();
        }

        // ---- compute stage s from buf ----
        const uint32_t aBase = sA + buf * 16384;
        const uint32_t bBase = sB + buf * 8192;
#pragma unroll
        for (int kh = 0; kh < 2; ++kh) {
            uint32_t bh[4], bl[4];
            {
                uint32_t addr = bBase + (uint32_t)(kh * 16 + kB) * 128
                              + (uint32_t)(((wn * 2 + cB) ^ swzB) << 4);
                LDSM_X4T(bh[0], bh[1], bh[2], bh[3], addr);
                LDSM_X4T(bl[0], bl[1], bl[2], bl[3], addr + 4096);
            }
#pragma unroll
            for (int mi = 0; mi < 4; ++mi) {
                const int R = wm * 64 + mi * 16;
                uint32_t ah[4], al[4];
                uint32_t addr = aBase + (uint32_t)(R + rowA) * 64
                              + (uint32_t)(((kh * 2 + cA) ^ swzA) << 4);
                LDSM_X4(ah[0], ah[1], ah[2], ah[3], addr);
                LDSM_X4(al[0], al[1], al[2], al[3], addr + 8192);
                // chains: Ah*Qh + Ah*Ql + Al*Qh
                MMA16816(acc[mi][0], ah[0],ah[1],ah[2],ah[3], bh[0],bh[1]);
                MMA16816(acc[mi][1], ah[0],ah[1],ah[2],ah[3], bh[2],bh[3]);
                MMA16816(acc[mi][0], ah[0],ah[1],ah[2],ah[3], bl[0],bl[1]);
                MMA16816(acc[mi][1], ah[0],ah[1],ah[2],ah[3], bl[2],bl[3]);
                MMA16816(acc[mi][0], al[0],al[1],al[2],al[3], bh[0],bh[1]);
                MMA16816(acc[mi][1], al[0],al[1],al[2],al[3], bh[2],bh[3]);
            }
        }

        if (more) storeA(buf ^ 1);
        CP_WAIT0();
        __syncthreads();
    }

    // ---- self-term: reduce 16 lanes sharing each row ----
#pragma unroll
    for (int i = 0; i < 8; ++i) {
        float v = selfAcc[i];
        v += __shfl_xor_sync(0xffffffffu, v, 1);
        v += __shfl_xor_sync(0xffffffffu, v, 2);
        v += __shfl_xor_sync(0xffffffffu, v, 4);
        v += __shfl_xor_sync(0xffffffffu, v, 8);
        if ((lane & 15) == 0)
            g_self[cI * K_A + kb + wid * 16 + 2 * i + lrow] = v * LN2F;
    }

    // ---- epilogue: transpose through smem, coalesced g_cross stores ----
    float* Csm = reinterpret_cast<float*>(smem);   // [64 q][128 m]
    const int g   = lane >> 2;
    const int tig = lane & 3;
#pragma unroll
    for (int mi = 0; mi < 4; ++mi) {
        const int r0 = wm * 64 + mi * 16 + g;
#pragma unroll
        for (int nh = 0; nh < 2; ++nh) {
            const int col = wn * 16 + nh * 8 + tig * 2;
            Csm[(col    ) * 128 + r0    ] = acc[mi][nh][0];
            Csm[(col + 1) * 128 + r0    ] = acc[mi][nh][1];
            Csm[(col    ) * 128 + r0 + 8] = acc[mi][nh][2];
            Csm[(col + 1) * 128 + r0 + 8] = acc[mi][nh][3];
        }
    }
    __syncthreads();
    {
        const int q  = tid >> 2;
        const int mb = (tid & 3) * 32;
        const float4* src = reinterpret_cast<const float4*>(Csm + q * 128 + mb);
        float4* dst = reinterpret_cast<float4*>(g_cross + ((size_t)(cI * B_Q + q)) * K_A + kb + mb);
#pragma unroll
        for (int j = 0; j < 8; ++j) dst[j] = src[j];
    }
}

// ---------------- Kernel C: fp64 combine + top-8 argmin + majority vote ----------------
__global__ void __launch_bounds__(256)
topk_kernel(const int* __restrict__ label, float* __restrict__ out) {
    __shared__ double kl[K_A];
    __shared__ double rv[256];
    __shared__ int    ri[256];
    const int b   = blockIdx.x;
    const int tid = threadIdx.x;

    for (int k = tid; k < K_A; k += 256) {
        double s = 0.0;
#pragma unroll
        for (int c = 0; c < DSPLIT; ++c)
            s += (double)g_self[c * K_A + k]
               - (double)g_cross[((size_t)(c * B_Q + b)) * K_A + k];
        kl[k] = s;   // = D * kl[b][k]
    }
    __syncthreads();

    int cnt1 = 0;
    for (int r = 0; r < KNN; ++r) {
        double bv = 1e300; int bi = K_A - 1;
        for (int k = tid; k < K_A; k += 256) {
            double v = kl[k];
            if (v < bv) { bv = v; bi = k; }
        }
        rv[tid] = bv; ri[tid] = bi;
        __syncthreads();
        for (int off = 128; off > 0; off >>= 1) {
            if (tid < off) {
                double v = rv[tid + off]; int i2 = ri[tid + off];
                if (v < rv[tid] || (v == rv[tid] && i2 < ri[tid])) { rv[tid] = v; ri[tid] = i2; }
            }
            __syncthreads();
        }
        int sel = ri[0];
        if (sel < 0)    sel = 0;
        if (sel >= K_A) sel = K_A - 1;
        cnt1 += label[sel];
        if (tid == 0) kl[sel] = 1e300;
        __syncthreads();
    }
    if (tid == 0) out[b] = (cnt1 > KNN / 2) ? 1.0f : 0.0f;
}

extern "C" void kernel_launch(void* const* d_in, const int* in_sizes, int n_in,
                              void* d_out, int out_size) {
    (void)in_sizes; (void)n_in; (void)out_size;
    const float* query  = (const float*)d_in[0];
    const float* anchor = (const float*)d_in[1];
    const int*   label  = (const int*)d_in[2];
    float* out = (float*)d_out;

    qlog_kernel<<<(B_Q * DPAD + 255) / 256, 256>>>(query);
    dim3 g(K_A / KTILE, DSPLIT);
    gemm_kernel<<<g, 256>>>(anchor);
    topk_kernel<<<B_Q, 256>>>(label, out);
}

// round 11
// speedup vs baseline: 2.0423x; 1.0647x over previous
#include <cuda_runtime.h>
#include <cuda_bf16.h>
#include <cstdint>

#define D_DIM   50257
#define B_Q     64
#define K_A     4096
#define KNN     8
#define EPSF    1e-10f
#define LN2F    0.69314718055994530942f

#define DSPLIT  9
#define DTILE   32
#define STAGES  175                  // ceil(50257 / (9*32))
#define CHUNK_D (STAGES * DTILE)     // 5600
#define DPAD    (DSPLIT * CHUNK_D)   // 50400
#define NTILES  (DPAD / DTILE)       // 1575
#define KTILE   128

// ---- static device scratch ----
__device__ __align__(16) unsigned short g_qB[NTILES * 4096]; // 12.9MB: per 32-d tile [qh 4KB][ql 4KB], swizzled
__device__ float g_cross[DSPLIT * B_Q * K_A];                // 9.4MB partial cross sums
__device__ float g_self [DSPLIT * K_A];

__device__ __forceinline__ uint32_t smem_u32(const void* p) {
    uint32_t a;
    asm("{ .reg .u64 t; cvta.to.shared.u64 t, %1; cvt.u32.u64 %0, t; }" : "=r"(a) : "l"(p));
    return a;
}

#define CP_ASYNC16(dst, src) asm volatile("cp.async.cg.shared.global [%0], [%1], 16;" :: "r"(dst), "l"(src))
#define CP_COMMIT()          asm volatile("cp.async.commit_group;" ::: "memory")
#define CP_WAIT0()           asm volatile("cp.async.wait_group 0;" ::: "memory")

#define LDSM_X4(r, a) \
    asm volatile("ldmatrix.sync.aligned.m8n8.x4.shared.b16 {%0,%1,%2,%3}, [%4];" \
        : "=r"((r)[0]),"=r"((r)[1]),"=r"((r)[2]),"=r"((r)[3]) : "r"(a))
#define LDSM_X4T(r, a) \
    asm volatile("ldmatrix.sync.aligned.m8n8.x4.trans.shared.b16 {%0,%1,%2,%3}, [%4];" \
        : "=r"((r)[0]),"=r"((r)[1]),"=r"((r)[2]),"=r"((r)[3]) : "r"(a))

#define MMA16816(c, a, b0, b1) \
    asm volatile("mma.sync.aligned.m16n8k16.row.col.f32.bf16.bf16.f32 " \
        "{%0,%1,%2,%3}, {%4,%5,%6,%7}, {%8,%9}, {%0,%1,%2,%3};" \
        : "+f"((c)[0]),"+f"((c)[1]),"+f"((c)[2]),"+f"((c)[3]) \
        : "r"((a)[0]),"r"((a)[1]),"r"((a)[2]),"r"((a)[3]), "r"(b0),"r"(b1))

// ---------------- Kernel A: qlog -> bf16 hi/lo tiles, smem-staged coalesced output ----------------
// One block per 32-d tile. Layout per tile (8KB): hi rows k=0..31 (128B of 64 n), 16B chunk c
// stored at c^(k&7); lo at +4096B. Matches GEMM's B-side ldmatrix swizzle.
__global__ void __launch_bounds__(256)
qlog_kernel(const float* __restrict__ q) {
    __shared__ __align__(16) unsigned short sh[32 * 64];
    __shared__ __align__(16) unsigned short sl[32 * 64];
    const int t    = blockIdx.x;
    const int lane = threadIdx.x & 31;
    const int w    = threadIdx.x >> 5;
    const int d    = t * DTILE + lane;
    const bool v   = d < D_DIM;
#pragma unroll
    for (int i = 0; i < 8; ++i) {
        const int b = w * 8 + i;
        float x = 0.f;
        if (v) x = __log2f(q[(size_t)b * D_DIM + d] + EPSF) * LN2F;   // coalesced 128B reads
        __nv_bfloat16 h = __float2bfloat16(x);
        __nv_bfloat16 l = __float2bfloat16(x - __bfloat162float(h));
        sh[lane * 64 + b] = __bfloat16_as_ushort(h);
        sl[lane * 64 + b] = __bfloat16_as_ushort(l);
    }
    __syncthreads();
    // write out: thread -> one 16B chunk; consecutive tid -> consecutive 16B (fully coalesced)
    const int k  = threadIdx.x >> 3;
    const int cs = threadIdx.x & 7;       // stored chunk
    const int c  = cs ^ (k & 7);          // source b-chunk (involution)
    uint4* tb = reinterpret_cast<uint4*>(g_qB + (size_t)t * 4096);
    tb[k * 8 + cs]       = reinterpret_cast<const uint4*>(sh + k * 64)[c];
    tb[256 + k * 8 + cs] = reinterpret_cast<const uint4*>(sl + k * 64)[c];
}

// ---------------- Kernel B: bf16 3-chain tensor-core GEMM + fused self-term ----------------
// smem 48KB: A [2 buf][hi|lo][128 r][32 k] bf16 (buf 16KB), B at +32768 [2 buf][hi|lo][32 k][64 n]
// Warp grid 4x2: warp tile 32(M) x 32(N).
__global__ void __launch_bounds__(256, 2)
gemm_kernel(const float* __restrict__ anchor) {
    __shared__ __align__(128) char smem[49152];
    const uint32_t sA = smem_u32(smem);
    const uint32_t sB = sA + 32768;

    const int tid  = threadIdx.x;
    const int lane = tid & 31;
    const int wid  = tid >> 5;
    const int wm   = wid >> 1;        // 0..3 : M quarter (32 rows)
    const int wn   = wid & 1;         // 0..1 : N half (32 cols)
    const int kb   = blockIdx.x * KTILE;
    const int cI   = blockIdx.y;
    const int dbase = cI * CHUNK_D;

    // loader mapping: warp owns rows wid*16..+15; lane: lrow = lane>>4, d-pair = lane&15
    const int lrow = lane >> 4;
    const int lcol = lane & 15;

    // ldmatrix lane constants
    const int rowA = lane & 15;
    const int cA   = lane >> 4;
    const int swzA = ((lane & 15) >> 1) & 3;
    const int kB   = lane & 15;
    const int cB   = lane >> 4;
    const int swzB = lane & 7;

    float acc[2][4][4];               // [mi][nh][frag]
#pragma unroll
    for (int mi = 0; mi < 2; ++mi)
#pragma unroll
        for (int nh = 0; nh < 4; ++nh)
#pragma unroll
            for (int r = 0; r < 4; ++r) acc[mi][nh][r] = 0.f;

    float selfAcc[8];
#pragma unroll
    for (int i = 0; i < 8; ++i) selfAcc[i] = 0.f;

    float2 va[8];

    auto loadA = [&](int s) {
        const int d0 = dbase + s * DTILE + 2 * lcol;
        const bool vx = d0 < D_DIM;
        const bool vy = d0 + 1 < D_DIM;
#pragma unroll
        for (int i = 0; i < 8; ++i) {
            const float* p = anchor + (size_t)(kb + wid * 16 + 2 * i + lrow) * D_DIM + d0;
            va[i].x = vx ? __ldg(p)     : 0.f;
            va[i].y = vy ? __ldg(p + 1) : 0.f;
        }
    };
    auto storeA = [&](int buf) {
        const uint32_t coff   = (uint32_t)(lcol >> 2);
        const uint32_t within = (uint32_t)(lcol & 3) * 4;
#pragma unroll
        for (int i = 0; i < 8; ++i) {
            const int r = wid * 16 + 2 * i + lrow;
            selfAcc[i] += va[i].x * __log2f(va[i].x + EPSF)
                        + va[i].y * __log2f(va[i].y + EPSF);
            __nv_bfloat16 hx = __float2bfloat16(va[i].x);
            __nv_bfloat16 hy = __float2bfloat16(va[i].y);
            __nv_bfloat16 lx = __float2bfloat16(va[i].x - __bfloat162float(hx));
            __nv_bfloat16 ly = __float2bfloat16(va[i].y - __bfloat162float(hy));
            uint32_t ph = (uint32_t)__bfloat16_as_ushort(hx) | ((uint32_t)__bfloat16_as_ushort(hy) << 16);
            uint32_t pl = (uint32_t)__bfloat16_as_ushort(lx) | ((uint32_t)__bfloat16_as_ushort(ly) << 16);
            uint32_t swz  = (uint32_t)((r >> 1) & 3);
            uint32_t byte = (uint32_t)r * 64 + ((coff ^ swz) << 4) + within;
            *(uint32_t*)(smem + buf * 16384 + byte)        = ph;
            *(uint32_t*)(smem + buf * 16384 + 8192 + byte) = pl;
        }
    };
    auto issueB = [&](int s, int buf) {
        const char* src = reinterpret_cast<const char*>(g_qB) + (size_t)(cI * STAGES + s) * 8192;
        uint32_t dst = sB + buf * 8192 + tid * 16;
        CP_ASYNC16(dst, src + tid * 16);
        CP_ASYNC16(dst + 4096, src + tid * 16 + 4096);
    };

    // prologue
    loadA(0);
    issueB(0, 0);
    CP_COMMIT();
    storeA(0);
    CP_WAIT0();
    __syncthreads();

    for (int s = 0; s < STAGES; ++s) {
        const int buf = s & 1;
        const bool more = (s + 1 < STAGES);
        if (more) {
            loadA(s + 1);
            issueB(s + 1, buf ^ 1);
            CP_COMMIT();
        }

        const uint32_t aBase = sA + buf * 16384;
        const uint32_t bBase = sB + buf * 8192;
#pragma unroll
        for (int kh = 0; kh < 2; ++kh) {
            uint32_t bh[2][4], bl[2][4], ah[2][4], al[2][4];
#pragma unroll
            for (int nc = 0; nc < 2; ++nc) {
                uint32_t addr = bBase + (uint32_t)(kh * 16 + kB) * 128
                              + (uint32_t)(((wn * 4 + nc * 2 + cB) ^ swzB) << 4);
                LDSM_X4T(bh[nc], addr);
                LDSM_X4T(bl[nc], addr + 4096);
            }
#pragma unroll
            for (int mi = 0; mi < 2; ++mi) {
                const int R = wm * 32 + mi * 16;
                uint32_t addr = aBase + (uint32_t)(R + rowA) * 64
                              + (uint32_t)(((kh * 2 + cA) ^ swzA) << 4);
                LDSM_X4(ah[mi], addr);
                LDSM_X4(al[mi], addr + 8192);
            }
            // chain-major issue: same-accumulator spacing = 8 MMAs (beats HMMA latency)
#pragma unroll
            for (int mi = 0; mi < 2; ++mi)
#pragma unroll
                for (int nc = 0; nc < 2; ++nc) {
                    MMA16816(acc[mi][2 * nc],     ah[mi], bh[nc][0], bh[nc][1]);
                    MMA16816(acc[mi][2 * nc + 1], ah[mi], bh[nc][2], bh[nc][3]);
                }
#pragma unroll
            for (int mi = 0; mi < 2; ++mi)
#pragma unroll
                for (int nc = 0; nc < 2; ++nc) {
                    MMA16816(acc[mi][2 * nc],     ah[mi], bl[nc][0], bl[nc][1]);
                    MMA16816(acc[mi][2 * nc + 1], ah[mi], bl[nc][2], bl[nc][3]);
                }
#pragma unroll
            for (int mi = 0; mi < 2; ++mi)
#pragma unroll
                for (int nc = 0; nc < 2; ++nc) {
                    MMA16816(acc[mi][2 * nc],     al[mi], bh[nc][0], bh[nc][1]);
                    MMA16816(acc[mi][2 * nc + 1], al[mi], bh[nc][2], bh[nc][3]);
                }
        }

        if (more) storeA(buf ^ 1);
        CP_WAIT0();
        __syncthreads();
    }

    // ---- self-term: reduce 16 lanes sharing each row ----
#pragma unroll
    for (int i = 0; i < 8; ++i) {
        float v = selfAcc[i];
        v += __shfl_xor_sync(0xffffffffu, v, 1);
        v += __shfl_xor_sync(0xffffffffu, v, 2);
        v += __shfl_xor_sync(0xffffffffu, v, 4);
        v += __shfl_xor_sync(0xffffffffu, v, 8);
        if ((lane & 15) == 0)
            g_self[cI * K_A + kb + wid * 16 + 2 * i + lrow] = v * LN2F;
    }

    // ---- epilogue: transpose through smem, coalesced g_cross stores ----
    float* Csm = reinterpret_cast<float*>(smem);   // [64 q][128 m]
    const int g   = lane >> 2;
    const int tig = lane & 3;
#pragma unroll
    for (int mi = 0; mi < 2; ++mi) {
        const int r0 = wm * 32 + mi * 16 + g;
#pragma unroll
        for (int nh = 0; nh < 4; ++nh) {
            const int col = wn * 32 + nh * 8 + tig * 2;
            Csm[(col    ) * 128 + r0    ] = acc[mi][nh][0];
            Csm[(col + 1) * 128 + r0    ] = acc[mi][nh][1];
            Csm[(col    ) * 128 + r0 + 8] = acc[mi][nh][2];
            Csm[(col + 1) * 128 + r0 + 8] = acc[mi][nh][3];
        }
    }
    __syncthreads();
    {
        const int qq = tid >> 2;
        const int mb = (tid & 3) * 32;
        const float4* src = reinterpret_cast<const float4*>(Csm + qq * 128 + mb);
        float4* dst = reinterpret_cast<float4*>(g_cross + ((size_t)(cI * B_Q + qq)) * K_A + kb + mb);
#pragma unroll
        for (int j = 0; j < 8; ++j) dst[j] = src[j];
    }
}

// ---------------- Kernel C: fp64 combine + top-8 argmin + majority vote ----------------
__global__ void __launch_bounds__(256)
topk_kernel(const int* __restrict__ label, float* __restrict__ out) {
    __shared__ double kl[K_A];
    __shared__ double rv[256];
    __shared__ int    ri[256];
    const int b   = blockIdx.x;
    const int tid = threadIdx.x;

    for (int k = tid; k < K_A; k += 256) {
        double s = 0.0;
#pragma unroll
        for (int c = 0; c < DSPLIT; ++c)
            s += (double)g_self[c * K_A + k]
               - (double)g_cross[((size_t)(c * B_Q + b)) * K_A + k];
        kl[k] = s;   // = D * kl[b][k]
    }
    __syncthreads();

    int cnt1 = 0;
    for (int r = 0; r < KNN; ++r) {
        double bv = 1e300; int bi = K_A - 1;
        for (int k = tid; k < K_A; k += 256) {
            double v = kl[k];
            if (v < bv) { bv = v; bi = k; }
        }
        rv[tid] = bv; ri[tid] = bi;
        __syncthreads();
        for (int off = 128; off > 0; off >>= 1) {
            if (tid < off) {
                double v = rv[tid + off]; int i2 = ri[tid + off];
                if (v < rv[tid] || (v == rv[tid] && i2 < ri[tid])) { rv[tid] = v; ri[tid] = i2; }
            }
            __syncthreads();
        }
        int sel = ri[0];
        if (sel < 0)    sel = 0;
        if (sel >= K_A) sel = K_A - 1;
        cnt1 += label[sel];
        if (tid == 0) kl[sel] = 1e300;
        __syncthreads();
    }
    if (tid == 0) out[b] = (cnt1 > KNN / 2) ? 1.0f : 0.0f;
}

extern "C" void kernel_launch(void* const* d_in, const int* in_sizes, int n_in,
                              void* d_out, int out_size) {
    (void)in_sizes; (void)n_in; (void)out_size;
    const float* query  = (const float*)d_in[0];
    const float* anchor = (const float*)d_in[1];
    const int*   label  = (const int*)d_in[2];
    float* out = (float*)d_out;

    qlog_kernel<<<NTILES, 256>>>(query);
    dim3 g(K_A / KTILE, DSPLIT);
    gemm_kernel<<<g, 256>>>(anchor);
    topk_kernel<<<B_Q, 256>>>(label, out);
}